// round 8
// baseline (speedup 1.0000x reference)
#include <cuda_runtime.h>
#include <math.h>

#define N_INST 128
#define NV     128
#define IMG    512
#define RES    64
#define SPLIT  8                    // 8 blocks per instance, 8 rows each
#define THREADS 128
#define PPT     4                   // 4 consecutive x per thread (one row)
#define NPAIR   (PPT/2)
#define NBLOCKS (N_INST*SPLIT)      // 1024
#define INV_S   0.1f
#define CULL_R  11.0f               // > sqrt(115.13)=10.73 -> clip-identical

typedef unsigned long long ull;

__device__ __forceinline__ ull f2add(ull a, ull b) {
    ull r; asm("add.rn.f32x2 %0,%1,%2;" : "=l"(r) : "l"(a), "l"(b)); return r;
}
__device__ __forceinline__ ull f2mul(ull a, ull b) {
    ull r; asm("mul.rn.f32x2 %0,%1,%2;" : "=l"(r) : "l"(a), "l"(b)); return r;
}
__device__ __forceinline__ ull f2fma(ull a, ull b, ull c) {
    ull r; asm("fma.rn.f32x2 %0,%1,%2,%3;" : "=l"(r) : "l"(a), "l"(b), "l"(c)); return r;
}
__device__ __forceinline__ ull fpack(float lo, float hi) {
    ull r; asm("mov.b64 %0,{%1,%2};" : "=l"(r) : "f"(lo), "f"(hi)); return r;
}
__device__ __forceinline__ void funpack(float& lo, float& hi, ull v) {
    asm("mov.b64 {%0,%1},%2;" : "=f"(lo), "=f"(hi) : "l"(v));
}
__device__ __forceinline__ float mulsat(float a, float b) {
    float r; asm("mul.rn.sat.f32 %0,%1,%2;" : "=f"(r) : "f"(a), "f"(b)); return r;
}

// Scratch (no allocations allowed)
__device__ float g_part[NBLOCKS*3];
__device__ int   g_count = 0;

__global__ __launch_bounds__(THREADS) void fused_kernel(
    const float* __restrict__ preds,
    const float* __restrict__ masks,
    const float* __restrict__ bboxes,
    float* __restrict__ out)
{
    int b     = blockIdx.x;
    int n     = b >> 3;
    int chunk = b & 7;
    int tid   = threadIdx.x;
    int wid   = tid >> 5, lid = tid & 31;

    __shared__ float4 s_A[NV+1];     // {-ax, ay, -abx, -aby}
    __shared__ float4 s_B[NV+1];     // {-invd, slope, by, ax}
    __shared__ float2 s_yr[NV];      // {ymin, ymax}
    __shared__ short  s_list[4][NV+4];
    __shared__ float  s_vx[NV], s_vy[NV];
    __shared__ float  s_red[16];
    __shared__ float  s_ub[4];
    __shared__ int    s_last;

    // ---- per-block prep: union box + normalized verts + segment params ----
    float2 pv = ((const float2*)preds)[n*NV + tid];
    float x = pv.x, y = pv.y;
    float mnx = x, mny = y, mxx = x, mxy = y;
#pragma unroll
    for (int o = 16; o > 0; o >>= 1) {
        mnx = fminf(mnx, __shfl_xor_sync(0xffffffffu, mnx, o));
        mny = fminf(mny, __shfl_xor_sync(0xffffffffu, mny, o));
        mxx = fmaxf(mxx, __shfl_xor_sync(0xffffffffu, mxx, o));
        mxy = fmaxf(mxy, __shfl_xor_sync(0xffffffffu, mxy, o));
    }
    if (lid == 0) { s_red[wid] = mnx; s_red[4+wid] = mny; s_red[8+wid] = mxx; s_red[12+wid] = mxy; }
    __syncthreads();
    if (tid == 0) {
        float a = fminf(fminf(s_red[0],  s_red[1]),  fminf(s_red[2],  s_red[3]));
        float c = fminf(fminf(s_red[4],  s_red[5]),  fminf(s_red[6],  s_red[7]));
        float d = fmaxf(fmaxf(s_red[8],  s_red[9]),  fmaxf(s_red[10], s_red[11]));
        float e = fmaxf(fmaxf(s_red[12], s_red[13]), fmaxf(s_red[14], s_red[15]));
        s_ub[0] = fminf(a, bboxes[n*4+0]);
        s_ub[1] = fminf(c, bboxes[n*4+1]);
        s_ub[2] = fmaxf(d, bboxes[n*4+2]);
        s_ub[3] = fmaxf(e, bboxes[n*4+3]);
        // sentinel NV: cond=false (both endpoints above all rows), d^2=+inf
        s_A[NV] = make_float4(0.0f, 1.0e30f, 0.0f, 0.0f);
        s_B[NV] = make_float4(0.0f, 0.0f, 1.0e30f, 0.0f);
    }
    __syncthreads();
    float ub0 = s_ub[0], ub1 = s_ub[1], ub2 = s_ub[2], ub3 = s_ub[3];
    float vx = (x - ub0) / (ub2 - ub0) * (float)RES - 0.5f;
    float vy = (y - ub1) / (ub3 - ub1) * (float)RES - 0.5f;
    s_vx[tid] = vx; s_vy[tid] = vy;
    __syncthreads();
    {
        int t1 = (tid + 1) & (NV - 1);
        float ax = vx, ay = vy;
        float bx = s_vx[t1], byv = s_vy[t1];
        float abx = bx - ax, aby = byv - ay;
        float invd = 1.0f / (abx*abx + aby*aby + 1e-12f);
        float sdy = (aby == 0.0f) ? 1.0f : aby;
        s_A[tid] = make_float4(-ax, ay, -abx, -aby);
        s_B[tid] = make_float4(-invd, abx / sdy, byv, ax);
        s_yr[tid] = make_float2(fminf(ay, byv), fmaxf(ay, byv));
    }
    __syncthreads();

    // ---- phase 1: per-warp survivor compaction (ballot + popc prefix) ----
    int cnt;
    {
        float band_lo = (float)(chunk * 8 + wid * 2);
        float band_hi = band_lo + 1.0f;
        float cull_lo = band_lo - CULL_R;
        float cull_hi = band_hi + CULL_R;
        cnt = 0;
#pragma unroll
        for (int base = 0; base < NV; base += 32) {
            int v = base + lid;
            float2 yr = s_yr[v];
            bool keep = (yr.y >= cull_lo) && (yr.x <= cull_hi);
            unsigned ball = __ballot_sync(0xffffffffu, keep);
            int pos = cnt + __popc(ball & ((1u << lid) - 1u));
            if (keep) s_list[wid][pos] = (short)v;
            cnt += __popc(ball);
        }
        // pad to multiple of 4 with sentinel
        if (lid == 0) {
            int c = cnt;
            while (c & 3) s_list[wid][c++] = (short)NV;
        }
        cnt = (cnt + 3) & ~3;
    }
    __syncwarp();

    // ---- phase 2: branch-free rasterize over survivors, unrolled x4 ----
    int row   = chunk * 8 + (tid >> 4);
    int xbase = (tid & 15) * PPT;
    float pyf = (float)row;
    float xbf = (float)xbase;

    ull px2[NPAIR];
    float d2min[PPT];
#pragma unroll
    for (int j = 0; j < NPAIR; j++)
        px2[j] = fpack(xbf + (float)(2*j), xbf + (float)(2*j+1));
#pragma unroll
    for (int k = 0; k < PPT; k++) d2min[k] = 3.4e38f;
    unsigned crossbits = 0;

    const short4* __restrict__ l4 = (const short4*)s_list[wid];
    for (int i = 0; i < cnt; i += 4) {
        short4 idx = l4[i >> 2];
        // batch all 8 param loads (one index-scoreboard wait, pipelined LDS)
        float4 A0 = s_A[idx.x], B0 = s_B[idx.x];
        float4 A1 = s_A[idx.y], B1 = s_B[idx.y];
        float4 A2 = s_A[idx.z], B2 = s_B[idx.z];
        float4 A3 = s_A[idx.w], B3 = s_B[idx.w];
#pragma unroll
        for (int u = 0; u < 4; u++) {
            float4 A = (u == 0) ? A0 : (u == 1) ? A1 : (u == 2) ? A2 : A3;
            float4 B = (u == 0) ? B0 : (u == 1) ? B1 : (u == 2) ? B2 : B3;
            float nax = A.x, ay = A.y, nabx = A.z, naby = A.w;
            float ninvd = B.x, slope = B.y, byv = B.z, ax = B.w;

            float pay     = pyf - ay;
            float payabyn = pay * naby;             // = -pay*aby
            ull nax2   = fpack(nax, nax);
            ull nabx2  = fpack(nabx, nabx);
            ull naby2  = fpack(naby, naby);
            ull pay2   = fpack(pay, pay);
            ull payn2  = fpack(payabyn, payabyn);

            // parity (once per thread per segment)
            bool  cond = (ay > pyf) != (byv > pyf);
            float xint = fmaf(pay, slope, ax);
            int   kk   = (int)ceilf(xint - xbf);
            kk = min(max(kk, 0), PPT);
            unsigned m = (1u << kk) - 1u;
            crossbits ^= cond ? m : 0u;

            // packed distance (2 pixels per iteration)
#pragma unroll
            for (int j = 0; j < NPAIR; j++) {
                ull pax2  = f2add(px2[j], nax2);
                ull dotn2 = f2fma(pax2, nabx2, payn2);   // = -dot
                float d0, d1; funpack(d0, d1, dotn2);
                float t0 = mulsat(d0, ninvd);            // sat(dot*invd)
                float t1 = mulsat(d1, ninvd);
                ull tc2 = fpack(t0, t1);
                ull dx2 = f2fma(tc2, nabx2, pax2);
                ull dy2 = f2fma(tc2, naby2, pay2);
                ull e2  = f2mul(dy2, dy2);
                ull q2  = f2fma(dx2, dx2, e2);
                float q0, q1; funpack(q0, q1, q2);
                d2min[2*j]   = fminf(d2min[2*j],   q0);
                d2min[2*j+1] = fminf(d2min[2*j+1], q1);
            }
        }
    }

    // ---- sigmoid + target bilinear + dice partials ----
    const float* __restrict__ mask = masks + (size_t)n * IMG * IMG;
    float ys = ub1 + (ub3 - ub1) * ((pyf + 0.5f) * (1.0f/(float)RES)) - 0.5f;
    float y0 = floorf(ys);
    float wy = ys - y0;
    int y0i = min(max((int)y0, 0), IMG-1);
    int y1i = min(y0i + 1, IMG-1);
    const float* r0 = mask + y0i*IMG;
    const float* r1 = mask + y1i*IMG;

    float inter = 0.0f, sp = 0.0f, st = 0.0f;
#pragma unroll
    for (int k = 0; k < PPT; k++) {
        float sign = (crossbits >> k) & 1u ? 1.0f : -1.0f;
        float xarg = sign * d2min[k] * INV_S;
        float pred = 1.0f / (1.0f + __expf(-xarg));
        pred = fminf(fmaxf(pred, 1e-5f), 0.99999f);

        float xs = ub0 + (ub2 - ub0) * ((xbf + (float)k + 0.5f) * (1.0f/(float)RES)) - 0.5f;
        float x0 = floorf(xs);
        float wx = xs - x0;
        int x0i = min(max((int)x0, 0), IMG-1);
        int x1i = min(x0i + 1, IMG-1);
        float m00 = r0[x0i], m01 = r0[x1i];
        float m10 = r1[x0i], m11 = r1[x1i];
        float val = (1.0f - wy) * ((1.0f - wx)*m00 + wx*m01)
                  +          wy * ((1.0f - wx)*m10 + wx*m11);
        float tgt = (val >= 0.5f) ? 1.0f : 0.0f;

        inter += pred * tgt;
        sp    += pred;
        st    += tgt;
    }

    // ---- deterministic block reduce ----
#pragma unroll
    for (int o = 16; o > 0; o >>= 1) {
        inter += __shfl_down_sync(0xffffffffu, inter, o);
        sp    += __shfl_down_sync(0xffffffffu, sp,    o);
        st    += __shfl_down_sync(0xffffffffu, st,    o);
    }
    __shared__ float r_i[4], r_p[4], r_t[4];
    if (lid == 0) { r_i[wid] = inter; r_p[wid] = sp; r_t[wid] = st; }
    __syncthreads();
    if (tid == 0) {
        float ti = r_i[0]+r_i[1]+r_i[2]+r_i[3];
        float tp = r_p[0]+r_p[1]+r_p[2]+r_p[3];
        float tt = r_t[0]+r_t[1]+r_t[2]+r_t[3];
        g_part[b*3+0] = ti;
        g_part[b*3+1] = tp;
        g_part[b*3+2] = tt;
        __threadfence();
        int old = atomicAdd(&g_count, 1);
        s_last = (old == NBLOCKS - 1) ? 1 : 0;
    }
    __syncthreads();

    // ---- last block finalizes: per-instance dice + mean ----
    if (s_last) {
        float fi = 0.0f, fp = 0.0f, ft = 0.0f;   // instance = tid
#pragma unroll
        for (int c = 0; c < SPLIT; c++) {
            int slot = ((tid << 3) + c) * 3;
            fi += __ldcg(&g_part[slot+0]);
            fp += __ldcg(&g_part[slot+1]);
            ft += __ldcg(&g_part[slot+2]);
        }
        float loss = 1.0f - (2.0f*fi + 1.0f) / (fp + ft + 1.0f);
        s_vx[tid] = loss;                        // reuse smem as scratch
        __syncthreads();
        for (int o = THREADS/2; o > 0; o >>= 1) {
            if (tid < o) s_vx[tid] += s_vx[tid + o];
            __syncthreads();
        }
        if (tid == 0) {
            out[0] = s_vx[0] * (1.0f / (float)N_INST);
            g_count = 0;                          // reset for next graph replay
        }
    }
}

extern "C" void kernel_launch(void* const* d_in, const int* in_sizes, int n_in,
                              void* d_out, int out_size) {
    const float* preds  = (const float*)d_in[0];
    const float* masks  = (const float*)d_in[1];
    const float* bboxes = (const float*)d_in[2];
    float* out = (float*)d_out;

    fused_kernel<<<NBLOCKS, THREADS>>>(preds, masks, bboxes, out);
}

// round 9
// speedup vs baseline: 1.5190x; 1.5190x over previous
#include <cuda_runtime.h>
#include <math.h>

#define N_INST 128
#define NV     128
#define IMG    512
#define RES    64
#define SPLIT  8                    // 8 blocks per instance, 8 rows each
#define THREADS 128
#define PPT     4                   // 4 consecutive x per thread (one row)
#define NPAIR   (PPT/2)
#define NBLOCKS (N_INST*SPLIT)      // 1024
#define INV_S   0.1f
#define CULL_R  11.0f               // > sqrt(115.13)=10.73 -> clip-identical

typedef unsigned long long ull;

__device__ __forceinline__ ull f2add(ull a, ull b) {
    ull r; asm("add.rn.f32x2 %0,%1,%2;" : "=l"(r) : "l"(a), "l"(b)); return r;
}
__device__ __forceinline__ ull f2mul(ull a, ull b) {
    ull r; asm("mul.rn.f32x2 %0,%1,%2;" : "=l"(r) : "l"(a), "l"(b)); return r;
}
__device__ __forceinline__ ull f2fma(ull a, ull b, ull c) {
    ull r; asm("fma.rn.f32x2 %0,%1,%2,%3;" : "=l"(r) : "l"(a), "l"(b), "l"(c)); return r;
}
__device__ __forceinline__ ull fpack(float lo, float hi) {
    ull r; asm("mov.b64 %0,{%1,%2};" : "=l"(r) : "f"(lo), "f"(hi)); return r;
}
__device__ __forceinline__ void funpack(float& lo, float& hi, ull v) {
    asm("mov.b64 {%0,%1},%2;" : "=f"(lo), "=f"(hi) : "l"(v));
}
__device__ __forceinline__ float mulsat(float a, float b) {
    float r; asm("mul.rn.sat.f32 %0,%1,%2;" : "=f"(r) : "f"(a), "f"(b)); return r;
}

// Scratch (no allocations allowed)
__device__ float g_part[NBLOCKS*3];
__device__ int   g_count = 0;

__global__ __launch_bounds__(THREADS) void fused_kernel(
    const float* __restrict__ preds,
    const float* __restrict__ masks,
    const float* __restrict__ bboxes,
    float* __restrict__ out)
{
    int b     = blockIdx.x;
    int n     = b >> 3;
    int chunk = b & 7;
    int tid   = threadIdx.x;
    int wid   = tid >> 5, lid = tid & 31;

    // DENSE (compacted) segment params — round-5 pre-duplicated layout
    __shared__ float4 s_pk0[NV+2];   // {-ax,-ax, abx,abx}
    __shared__ float4 s_pk1[NV+2];   // {-abx,-abx, -aby,-aby}
    __shared__ float4 s_sc[NV+2];    // {ay, aby, invd, by}
    __shared__ float2 s_par[NV+2];   // {slope, ax}
    __shared__ float  s_vx[NV], s_vy[NV];
    __shared__ float  s_red[16];
    __shared__ float  s_ub[4];
    __shared__ int    s_wcnt[4];
    __shared__ int    s_last;

    // ---- per-block prep: union box + normalized verts ----
    float2 pv = ((const float2*)preds)[n*NV + tid];
    float x = pv.x, y = pv.y;
    float mnx = x, mny = y, mxx = x, mxy = y;
#pragma unroll
    for (int o = 16; o > 0; o >>= 1) {
        mnx = fminf(mnx, __shfl_xor_sync(0xffffffffu, mnx, o));
        mny = fminf(mny, __shfl_xor_sync(0xffffffffu, mny, o));
        mxx = fmaxf(mxx, __shfl_xor_sync(0xffffffffu, mxx, o));
        mxy = fmaxf(mxy, __shfl_xor_sync(0xffffffffu, mxy, o));
    }
    if (lid == 0) { s_red[wid] = mnx; s_red[4+wid] = mny; s_red[8+wid] = mxx; s_red[12+wid] = mxy; }
    __syncthreads();
    if (tid == 0) {
        float a = fminf(fminf(s_red[0],  s_red[1]),  fminf(s_red[2],  s_red[3]));
        float c = fminf(fminf(s_red[4],  s_red[5]),  fminf(s_red[6],  s_red[7]));
        float d = fmaxf(fmaxf(s_red[8],  s_red[9]),  fmaxf(s_red[10], s_red[11]));
        float e = fmaxf(fmaxf(s_red[12], s_red[13]), fmaxf(s_red[14], s_red[15]));
        s_ub[0] = fminf(a, bboxes[n*4+0]);
        s_ub[1] = fminf(c, bboxes[n*4+1]);
        s_ub[2] = fmaxf(d, bboxes[n*4+2]);
        s_ub[3] = fmaxf(e, bboxes[n*4+3]);
    }
    __syncthreads();
    float ub0 = s_ub[0], ub1 = s_ub[1], ub2 = s_ub[2], ub3 = s_ub[3];
    float vx = (x - ub0) / (ub2 - ub0) * (float)RES - 0.5f;
    float vy = (y - ub1) / (ub3 - ub1) * (float)RES - 0.5f;
    s_vx[tid] = vx; s_vy[tid] = vy;
    __syncthreads();

    // ---- segment params in registers + block-level cull + dense compaction ----
    // block band: rows [chunk*8, chunk*8+7], cull radius 11 (clip-identical)
    float ax, ay, abx, aby, invd, slope, byv;
    bool keep;
    {
        int t1 = (tid + 1) & (NV - 1);
        ax = vx; ay = vy;
        float bx = s_vx[t1]; byv = s_vy[t1];
        abx = bx - ax; aby = byv - ay;
        invd = 1.0f / (abx*abx + aby*aby + 1e-12f);
        float sdy = (aby == 0.0f) ? 1.0f : aby;
        slope = abx / sdy;
        float ymin = fminf(ay, byv);
        float ymax = fmaxf(ay, byv);
        float cull_lo = (float)(chunk * 8)     - CULL_R;
        float cull_hi = (float)(chunk * 8 + 7) + CULL_R;
        keep = (ymax >= cull_lo) && (ymin <= cull_hi);
    }
    unsigned ball = __ballot_sync(0xffffffffu, keep);
    if (lid == 0) s_wcnt[wid] = __popc(ball);
    __syncthreads();
    int cnt = s_wcnt[0] + s_wcnt[1] + s_wcnt[2] + s_wcnt[3];
    {
        int wbase = 0;
#pragma unroll
        for (int w = 0; w < 4; w++) wbase += (w < wid) ? s_wcnt[w] : 0;
        int pos = wbase + __popc(ball & ((1u << lid) - 1u));
        if (keep) {
            s_pk0[pos] = make_float4(-ax, -ax, abx, abx);
            s_pk1[pos] = make_float4(-abx, -abx, -aby, -aby);
            s_sc[pos]  = make_float4(ay, aby, invd, byv);
            s_par[pos] = make_float2(slope, ax);
        }
        // sentinel pad (neutral: cond=false, d^2 huge)
        if (tid == 0) {
            s_pk0[cnt]   = make_float4(0.f, 0.f, 0.f, 0.f);
            s_pk1[cnt]   = make_float4(0.f, 0.f, 0.f, 0.f);
            s_sc[cnt]    = make_float4(1.0e30f, 0.f, 0.f, 1.0e30f);
            s_par[cnt]   = make_float2(0.f, 0.f);
            s_pk0[cnt+1] = make_float4(0.f, 0.f, 0.f, 0.f);
            s_pk1[cnt+1] = make_float4(0.f, 0.f, 0.f, 0.f);
            s_sc[cnt+1]  = make_float4(1.0e30f, 0.f, 0.f, 1.0e30f);
            s_par[cnt+1] = make_float2(0.f, 0.f);
        }
    }
    int cntp = (cnt + 1) & ~1;   // even trip count for x2 unroll
    __syncthreads();

    // ---- rasterize: one row of 4 consecutive pixels per thread ----
    int row   = chunk * 8 + (tid >> 4);
    int xbase = (tid & 15) * PPT;
    float pyf = (float)row;
    float xbf = (float)xbase;

    ull px2[NPAIR];
    float d2min[PPT];
#pragma unroll
    for (int j = 0; j < NPAIR; j++)
        px2[j] = fpack(xbf + (float)(2*j), xbf + (float)(2*j+1));
#pragma unroll
    for (int k = 0; k < PPT; k++) d2min[k] = 3.4e38f;
    unsigned crossbits = 0;

    for (int v = 0; v < cntp; v += 2) {
#pragma unroll
        for (int u = 0; u < 2; u++) {
            int vv = v + u;
            float4 p0 = s_pk0[vv];
            float4 p1 = s_pk1[vv];
            float4 sc = s_sc[vv];
            float2 pr = s_par[vv];
            ull nax2  = fpack(p0.x, p0.y);
            ull abx2  = fpack(p0.z, p0.w);
            ull nabx2 = fpack(p1.x, p1.y);
            ull naby2 = fpack(p1.z, p1.w);
            float say = sc.x, saby = sc.y, sinvd = sc.z, sby = sc.w;
            float sslope = pr.x, sax = pr.y;

            float pay    = pyf - say;
            float payaby = pay * saby;
            ull pay2     = fpack(pay, pay);
            ull payaby2  = fpack(payaby, payaby);

            // parity (once per thread per segment)
            bool  cond = (say > pyf) != (sby > pyf);
            float xint = fmaf(pay, sslope, sax);
            int   kk   = (int)ceilf(xint - xbf);
            kk = min(max(kk, 0), PPT);
            unsigned m = (1u << kk) - 1u;
            crossbits ^= cond ? m : 0u;

            // packed distance (2 pixels per iteration)
#pragma unroll
            for (int j = 0; j < NPAIR; j++) {
                ull pax2 = f2add(px2[j], nax2);
                ull dot2 = f2fma(pax2, abx2, payaby2);
                float d0, d1; funpack(d0, d1, dot2);
                float t0 = mulsat(d0, sinvd);
                float t1 = mulsat(d1, sinvd);
                ull tc2 = fpack(t0, t1);
                ull dx2 = f2fma(tc2, nabx2, pax2);
                ull dy2 = f2fma(tc2, naby2, pay2);
                ull e2  = f2mul(dy2, dy2);
                ull q2  = f2fma(dx2, dx2, e2);
                float q0, q1; funpack(q0, q1, q2);
                d2min[2*j]   = fminf(d2min[2*j],   q0);
                d2min[2*j+1] = fminf(d2min[2*j+1], q1);
            }
        }
    }

    // ---- sigmoid + target bilinear + dice partials ----
    const float* __restrict__ mask = masks + (size_t)n * IMG * IMG;
    float ys = ub1 + (ub3 - ub1) * ((pyf + 0.5f) * (1.0f/(float)RES)) - 0.5f;
    float y0 = floorf(ys);
    float wy = ys - y0;
    int y0i = min(max((int)y0, 0), IMG-1);
    int y1i = min(y0i + 1, IMG-1);
    const float* r0 = mask + y0i*IMG;
    const float* r1 = mask + y1i*IMG;

    float inter = 0.0f, sp = 0.0f, st = 0.0f;
#pragma unroll
    for (int k = 0; k < PPT; k++) {
        float sign = (crossbits >> k) & 1u ? 1.0f : -1.0f;
        float xarg = sign * d2min[k] * INV_S;
        float pred = 1.0f / (1.0f + __expf(-xarg));
        pred = fminf(fmaxf(pred, 1e-5f), 0.99999f);

        float xs = ub0 + (ub2 - ub0) * ((xbf + (float)k + 0.5f) * (1.0f/(float)RES)) - 0.5f;
        float x0 = floorf(xs);
        float wx = xs - x0;
        int x0i = min(max((int)x0, 0), IMG-1);
        int x1i = min(x0i + 1, IMG-1);
        float m00 = r0[x0i], m01 = r0[x1i];
        float m10 = r1[x0i], m11 = r1[x1i];
        float val = (1.0f - wy) * ((1.0f - wx)*m00 + wx*m01)
                  +          wy * ((1.0f - wx)*m10 + wx*m11);
        float tgt = (val >= 0.5f) ? 1.0f : 0.0f;

        inter += pred * tgt;
        sp    += pred;
        st    += tgt;
    }

    // ---- deterministic block reduce ----
#pragma unroll
    for (int o = 16; o > 0; o >>= 1) {
        inter += __shfl_down_sync(0xffffffffu, inter, o);
        sp    += __shfl_down_sync(0xffffffffu, sp,    o);
        st    += __shfl_down_sync(0xffffffffu, st,    o);
    }
    __shared__ float r_i[4], r_p[4], r_t[4];
    if (lid == 0) { r_i[wid] = inter; r_p[wid] = sp; r_t[wid] = st; }
    __syncthreads();
    if (tid == 0) {
        float ti = r_i[0]+r_i[1]+r_i[2]+r_i[3];
        float tp = r_p[0]+r_p[1]+r_p[2]+r_p[3];
        float tt = r_t[0]+r_t[1]+r_t[2]+r_t[3];
        g_part[b*3+0] = ti;
        g_part[b*3+1] = tp;
        g_part[b*3+2] = tt;
        __threadfence();
        int old = atomicAdd(&g_count, 1);
        s_last = (old == NBLOCKS - 1) ? 1 : 0;
    }
    __syncthreads();

    // ---- last block finalizes: per-instance dice + mean ----
    if (s_last) {
        float fi = 0.0f, fp = 0.0f, ft = 0.0f;   // instance = tid
#pragma unroll
        for (int c = 0; c < SPLIT; c++) {
            int slot = ((tid << 3) + c) * 3;
            fi += __ldcg(&g_part[slot+0]);
            fp += __ldcg(&g_part[slot+1]);
            ft += __ldcg(&g_part[slot+2]);
        }
        float loss = 1.0f - (2.0f*fi + 1.0f) / (fp + ft + 1.0f);
        s_vx[tid] = loss;                        // reuse smem as scratch
        __syncthreads();
        for (int o = THREADS/2; o > 0; o >>= 1) {
            if (tid < o) s_vx[tid] += s_vx[tid + o];
            __syncthreads();
        }
        if (tid == 0) {
            out[0] = s_vx[0] * (1.0f / (float)N_INST);
            g_count = 0;                          // reset for next graph replay
        }
    }
}

extern "C" void kernel_launch(void* const* d_in, const int* in_sizes, int n_in,
                              void* d_out, int out_size) {
    const float* preds  = (const float*)d_in[0];
    const float* masks  = (const float*)d_in[1];
    const float* bboxes = (const float*)d_in[2];
    float* out = (float*)d_out;

    fused_kernel<<<NBLOCKS, THREADS>>>(preds, masks, bboxes, out);
}

// round 10
// speedup vs baseline: 1.5984x; 1.0523x over previous
#include <cuda_runtime.h>
#include <math.h>

#define N_INST 128
#define NV     128
#define IMG    512
#define RES    64
#define SPLIT  8                    // 8 blocks per instance, 8 rows each
#define THREADS 128
#define PPT     4                   // 4 consecutive x per thread (one row)
#define NPAIR   (PPT/2)
#define NBLOCKS (N_INST*SPLIT)      // 1024
#define INV_S   0.1f
#define CULL_R  11.0f               // > sqrt(115.13)=10.73 -> clip-identical

typedef unsigned long long ull;

__device__ __forceinline__ ull f2add(ull a, ull b) {
    ull r; asm("add.rn.f32x2 %0,%1,%2;" : "=l"(r) : "l"(a), "l"(b)); return r;
}
__device__ __forceinline__ ull f2mul(ull a, ull b) {
    ull r; asm("mul.rn.f32x2 %0,%1,%2;" : "=l"(r) : "l"(a), "l"(b)); return r;
}
__device__ __forceinline__ ull f2fma(ull a, ull b, ull c) {
    ull r; asm("fma.rn.f32x2 %0,%1,%2,%3;" : "=l"(r) : "l"(a), "l"(b), "l"(c)); return r;
}
__device__ __forceinline__ ull fpack(float lo, float hi) {
    ull r; asm("mov.b64 %0,{%1,%2};" : "=l"(r) : "f"(lo), "f"(hi)); return r;
}
__device__ __forceinline__ void funpack(float& lo, float& hi, ull v) {
    asm("mov.b64 {%0,%1},%2;" : "=f"(lo), "=f"(hi) : "l"(v));
}
__device__ __forceinline__ float mulsat(float a, float b) {
    float r; asm("mul.rn.sat.f32 %0,%1,%2;" : "=f"(r) : "f"(a), "f"(b)); return r;
}

// Scratch (no allocations allowed)
__device__ float g_part[NBLOCKS*3];
__device__ int   g_count = 0;

__global__ __launch_bounds__(THREADS) void fused_kernel(
    const float* __restrict__ preds,
    const float* __restrict__ masks,
    const float* __restrict__ bboxes,
    float* __restrict__ out)
{
    int b     = blockIdx.x;
    int n     = b >> 3;
    int chunk = b & 7;
    int tid   = threadIdx.x;
    int wid   = tid >> 5, lid = tid & 31;

    // DENSE distance-only list (pre-duplicated lanes)
    __shared__ float4 s_pk0[NV+2];   // {-ax,-ax, abx,abx}
    __shared__ float4 s_pk1[NV+2];   // {-abx,-abx, -aby,-aby}
    __shared__ float4 s_sc[NV+2];    // {ay, aby, invd, pad}
    // DENSE parity-only list
    __shared__ float4 s_pp[NV+2];    // {ay, by, slope, ax}
    __shared__ float  s_vx[NV], s_vy[NV];
    __shared__ float  s_red[16];
    __shared__ float  s_ub[4];
    __shared__ int    s_wcnt[4], s_wcnp[4];
    __shared__ int    s_last;

    // ---- per-block prep: union box + normalized verts ----
    float2 pv = ((const float2*)preds)[n*NV + tid];
    float x = pv.x, y = pv.y;
    float mnx = x, mny = y, mxx = x, mxy = y;
#pragma unroll
    for (int o = 16; o > 0; o >>= 1) {
        mnx = fminf(mnx, __shfl_xor_sync(0xffffffffu, mnx, o));
        mny = fminf(mny, __shfl_xor_sync(0xffffffffu, mny, o));
        mxx = fmaxf(mxx, __shfl_xor_sync(0xffffffffu, mxx, o));
        mxy = fmaxf(mxy, __shfl_xor_sync(0xffffffffu, mxy, o));
    }
    if (lid == 0) { s_red[wid] = mnx; s_red[4+wid] = mny; s_red[8+wid] = mxx; s_red[12+wid] = mxy; }
    __syncthreads();
    if (tid == 0) {
        float a = fminf(fminf(s_red[0],  s_red[1]),  fminf(s_red[2],  s_red[3]));
        float c = fminf(fminf(s_red[4],  s_red[5]),  fminf(s_red[6],  s_red[7]));
        float d = fmaxf(fmaxf(s_red[8],  s_red[9]),  fmaxf(s_red[10], s_red[11]));
        float e = fmaxf(fmaxf(s_red[12], s_red[13]), fmaxf(s_red[14], s_red[15]));
        s_ub[0] = fminf(a, bboxes[n*4+0]);
        s_ub[1] = fminf(c, bboxes[n*4+1]);
        s_ub[2] = fmaxf(d, bboxes[n*4+2]);
        s_ub[3] = fmaxf(e, bboxes[n*4+3]);
    }
    __syncthreads();
    float ub0 = s_ub[0], ub1 = s_ub[1], ub2 = s_ub[2], ub3 = s_ub[3];
    float vx = (x - ub0) / (ub2 - ub0) * (float)RES - 0.5f;
    float vy = (y - ub1) / (ub3 - ub1) * (float)RES - 0.5f;
    s_vx[tid] = vx; s_vy[tid] = vy;
    __syncthreads();

    // ---- segment params + two block-level culls + dense compaction ----
    float ax, ay, abx, aby, invd, slope, byv;
    bool keep_d, keep_p;
    {
        int t1 = (tid + 1) & (NV - 1);
        ax = vx; ay = vy;
        float bx = s_vx[t1]; byv = s_vy[t1];
        abx = bx - ax; aby = byv - ay;
        invd = 1.0f / (abx*abx + aby*aby + 1e-12f);
        float sdy = (aby == 0.0f) ? 1.0f : aby;
        slope = abx / sdy;
        float ymin = fminf(ay, byv);
        float ymax = fmaxf(ay, byv);
        float r0f = (float)(chunk * 8);
        float r1f = (float)(chunk * 8 + 7);
        // distance: clip-identical beyond CULL_R from the band
        keep_d = (ymax >= r0f - CULL_R) && (ymin <= r1f + CULL_R);
        // parity: cond true for some row py in [r0,r1] iff ymin <= py < ymax
        keep_p = (ymax > r0f) && (ymin <= r1f);
    }
    unsigned bal_d = __ballot_sync(0xffffffffu, keep_d);
    unsigned bal_p = __ballot_sync(0xffffffffu, keep_p);
    if (lid == 0) { s_wcnt[wid] = __popc(bal_d); s_wcnp[wid] = __popc(bal_p); }
    __syncthreads();
    int cnt_d = s_wcnt[0] + s_wcnt[1] + s_wcnt[2] + s_wcnt[3];
    int cnt_p = s_wcnp[0] + s_wcnp[1] + s_wcnp[2] + s_wcnp[3];
    {
        int wb_d = 0, wb_p = 0;
#pragma unroll
        for (int w = 0; w < 4; w++) {
            wb_d += (w < wid) ? s_wcnt[w] : 0;
            wb_p += (w < wid) ? s_wcnp[w] : 0;
        }
        if (keep_d) {
            int pos = wb_d + __popc(bal_d & ((1u << lid) - 1u));
            s_pk0[pos] = make_float4(-ax, -ax, abx, abx);
            s_pk1[pos] = make_float4(-abx, -abx, -aby, -aby);
            s_sc[pos]  = make_float4(ay, aby, invd, 0.0f);
        }
        if (keep_p) {
            int pos = wb_p + __popc(bal_p & ((1u << lid) - 1u));
            s_pp[pos]  = make_float4(ay, byv, slope, ax);
        }
        if (tid == 0) {
            // distance sentinels: d^2 huge
            s_pk0[cnt_d]   = make_float4(0.f, 0.f, 0.f, 0.f);
            s_pk1[cnt_d]   = make_float4(0.f, 0.f, 0.f, 0.f);
            s_sc[cnt_d]    = make_float4(1.0e30f, 0.f, 0.f, 0.f);
            s_pk0[cnt_d+1] = make_float4(0.f, 0.f, 0.f, 0.f);
            s_pk1[cnt_d+1] = make_float4(0.f, 0.f, 0.f, 0.f);
            s_sc[cnt_d+1]  = make_float4(1.0e30f, 0.f, 0.f, 0.f);
            // parity sentinels: both endpoints above every row -> cond false
            s_pp[cnt_p]    = make_float4(1.0e30f, 1.0e30f, 0.f, 0.f);
            s_pp[cnt_p+1]  = make_float4(1.0e30f, 1.0e30f, 0.f, 0.f);
        }
    }
    int cntd = (cnt_d + 1) & ~1;
    int cntp = (cnt_p + 1) & ~1;
    __syncthreads();

    // ---- rasterize: one row of 4 consecutive pixels per thread ----
    int row   = chunk * 8 + (tid >> 4);
    int xbase = (tid & 15) * PPT;
    float pyf = (float)row;
    float xbf = (float)xbase;

    ull px2[NPAIR];
    float d2min[PPT];
#pragma unroll
    for (int j = 0; j < NPAIR; j++)
        px2[j] = fpack(xbf + (float)(2*j), xbf + (float)(2*j+1));
#pragma unroll
    for (int k = 0; k < PPT; k++) d2min[k] = 3.4e38f;

    // main loop: distance only
    for (int v = 0; v < cntd; v += 2) {
#pragma unroll
        for (int u = 0; u < 2; u++) {
            int vv = v + u;
            float4 p0 = s_pk0[vv];
            float4 p1 = s_pk1[vv];
            float4 sc = s_sc[vv];
            ull nax2  = fpack(p0.x, p0.y);
            ull abx2  = fpack(p0.z, p0.w);
            ull nabx2 = fpack(p1.x, p1.y);
            ull naby2 = fpack(p1.z, p1.w);
            float say = sc.x, saby = sc.y, sinvd = sc.z;

            float pay    = pyf - say;
            float payaby = pay * saby;
            ull pay2     = fpack(pay, pay);
            ull payaby2  = fpack(payaby, payaby);

#pragma unroll
            for (int j = 0; j < NPAIR; j++) {
                ull pax2 = f2add(px2[j], nax2);
                ull dot2 = f2fma(pax2, abx2, payaby2);
                float d0, d1; funpack(d0, d1, dot2);
                float t0 = mulsat(d0, sinvd);
                float t1 = mulsat(d1, sinvd);
                ull tc2 = fpack(t0, t1);
                ull dx2 = f2fma(tc2, nabx2, pax2);
                ull dy2 = f2fma(tc2, naby2, pay2);
                ull e2  = f2mul(dy2, dy2);
                ull q2  = f2fma(dx2, dx2, e2);
                float q0, q1; funpack(q0, q1, q2);
                d2min[2*j]   = fminf(d2min[2*j],   q0);
                d2min[2*j+1] = fminf(d2min[2*j+1], q1);
            }
        }
    }

    // parity loop: tiny straddle list
    unsigned crossbits = 0;
    for (int v = 0; v < cntp; v += 2) {
#pragma unroll
        for (int u = 0; u < 2; u++) {
            float4 q = s_pp[v + u];     // {ay, by, slope, ax}
            float pay  = pyf - q.x;
            bool  cond = (q.x > pyf) != (q.y > pyf);
            float xint = fmaf(pay, q.z, q.w);
            int   kk   = (int)ceilf(xint - xbf);
            kk = min(max(kk, 0), PPT);
            unsigned m = (1u << kk) - 1u;
            crossbits ^= cond ? m : 0u;
        }
    }

    // ---- sigmoid + target bilinear + dice partials ----
    const float* __restrict__ mask = masks + (size_t)n * IMG * IMG;
    float ys = ub1 + (ub3 - ub1) * ((pyf + 0.5f) * (1.0f/(float)RES)) - 0.5f;
    float y0 = floorf(ys);
    float wy = ys - y0;
    int y0i = min(max((int)y0, 0), IMG-1);
    int y1i = min(y0i + 1, IMG-1);
    const float* r0p = mask + y0i*IMG;
    const float* r1p = mask + y1i*IMG;

    float inter = 0.0f, sp = 0.0f, st = 0.0f;
#pragma unroll
    for (int k = 0; k < PPT; k++) {
        float sign = (crossbits >> k) & 1u ? 1.0f : -1.0f;
        float xarg = sign * d2min[k] * INV_S;
        float pred = 1.0f / (1.0f + __expf(-xarg));
        pred = fminf(fmaxf(pred, 1e-5f), 0.99999f);

        float xs = ub0 + (ub2 - ub0) * ((xbf + (float)k + 0.5f) * (1.0f/(float)RES)) - 0.5f;
        float x0 = floorf(xs);
        float wx = xs - x0;
        int x0i = min(max((int)x0, 0), IMG-1);
        int x1i = min(x0i + 1, IMG-1);
        float m00 = r0p[x0i], m01 = r0p[x1i];
        float m10 = r1p[x0i], m11 = r1p[x1i];
        float val = (1.0f - wy) * ((1.0f - wx)*m00 + wx*m01)
                  +          wy * ((1.0f - wx)*m10 + wx*m11);
        float tgt = (val >= 0.5f) ? 1.0f : 0.0f;

        inter += pred * tgt;
        sp    += pred;
        st    += tgt;
    }

    // ---- deterministic block reduce ----
#pragma unroll
    for (int o = 16; o > 0; o >>= 1) {
        inter += __shfl_down_sync(0xffffffffu, inter, o);
        sp    += __shfl_down_sync(0xffffffffu, sp,    o);
        st    += __shfl_down_sync(0xffffffffu, st,    o);
    }
    __shared__ float r_i[4], r_p[4], r_t[4];
    if (lid == 0) { r_i[wid] = inter; r_p[wid] = sp; r_t[wid] = st; }
    __syncthreads();
    if (tid == 0) {
        float ti = r_i[0]+r_i[1]+r_i[2]+r_i[3];
        float tp = r_p[0]+r_p[1]+r_p[2]+r_p[3];
        float tt = r_t[0]+r_t[1]+r_t[2]+r_t[3];
        g_part[b*3+0] = ti;
        g_part[b*3+1] = tp;
        g_part[b*3+2] = tt;
        __threadfence();
        int old = atomicAdd(&g_count, 1);
        s_last = (old == NBLOCKS - 1) ? 1 : 0;
    }
    __syncthreads();

    // ---- last block finalizes: per-instance dice + mean ----
    if (s_last) {
        float fi = 0.0f, fp = 0.0f, ft = 0.0f;   // instance = tid
#pragma unroll
        for (int c = 0; c < SPLIT; c++) {
            int slot = ((tid << 3) + c) * 3;
            fi += __ldcg(&g_part[slot+0]);
            fp += __ldcg(&g_part[slot+1]);
            ft += __ldcg(&g_part[slot+2]);
        }
        float loss = 1.0f - (2.0f*fi + 1.0f) / (fp + ft + 1.0f);
        s_vx[tid] = loss;                        // reuse smem as scratch
        __syncthreads();
        for (int o = THREADS/2; o > 0; o >>= 1) {
            if (tid < o) s_vx[tid] += s_vx[tid + o];
            __syncthreads();
        }
        if (tid == 0) {
            out[0] = s_vx[0] * (1.0f / (float)N_INST);
            g_count = 0;                          // reset for next graph replay
        }
    }
}

extern "C" void kernel_launch(void* const* d_in, const int* in_sizes, int n_in,
                              void* d_out, int out_size) {
    const float* preds  = (const float*)d_in[0];
    const float* masks  = (const float*)d_in[1];
    const float* bboxes = (const float*)d_in[2];
    float* out = (float*)d_out;

    fused_kernel<<<NBLOCKS, THREADS>>>(preds, masks, bboxes, out);
}